// round 4
// baseline (speedup 1.0000x reference)
#include <cuda_runtime.h>

#define TBLOCK  256
#define ITEMS   2
#define NFILT   11
#define NCOLS   262144
#define NROWS   128

typedef unsigned long long u64;

__device__ __forceinline__ u64 pack2(float lo, float hi) {
    u64 r;
    asm("mov.b64 %0, {%1, %2};" : "=l"(r) : "f"(lo), "f"(hi));
    return r;
}
__device__ __forceinline__ void unpack2(u64 v, float& lo, float& hi) {
    asm("mov.b64 {%0, %1}, %2;" : "=f"(lo), "=f"(hi) : "l"(v));
}
__device__ __forceinline__ u64 fma2(u64 a, u64 b, u64 c) {
    u64 d;
    asm("fma.rn.f32x2 %0, %1, %2, %3;" : "=l"(d) : "l"(a), "l"(b), "l"(c));
    return d;
}

// ITEMS=2: per-thread window = complexes [c0-6, c0+8) = 7 float4, lane stride
// 16B -> every LDG.128 is fully dense. One dense STG.128 out. No smem.
__global__ void __launch_bounds__(TBLOCK) fir_complex_dense_kernel(
    const float2* __restrict__ X, const float* __restrict__ phi,
    float2* __restrict__ Y)
{
    const int row  = blockIdx.y;
    const int gtid = blockIdx.x * TBLOCK + threadIdx.x;   // float4-pair index
    const int c0   = 2 * gtid;                            // first output column
    const float2* __restrict__ xrow = X + (size_t)row * NCOLS;
    float2* __restrict__ yrow       = Y + (size_t)row * NCOLS;

    // Coefficients A[k] = (wr_k, wi_k) — phi's native layout.
    u64 A[NFILT];
#pragma unroll
    for (int k = 0; k < NFILT; k++) {
        float2 w = __ldg(((const float2*)phi) + k);
        A[k] = pack2(w.x, w.y);
    }

    // Window: complex j (j=0..13) = column c0 - 6 + j, as 7 float4.
    float4 v[7];
    const int fb = gtid - 3;                 // first float4 index (= complexes 2fb, 2fb+1)
    if (fb >= 0 && fb + 7 <= NCOLS / 2) {
        const float4* x4 = (const float4*)xrow;
#pragma unroll
        for (int q = 0; q < 7; q++) v[q] = __ldg(x4 + fb + q);
    } else {
#pragma unroll
        for (int q = 0; q < 7; q++) {
            int ca = c0 - 6 + 2 * q;         // complex index of v[q].xy
            float2 a = (ca     >= 0 && ca     < NCOLS) ? xrow[ca]     : make_float2(0.f, 0.f);
            float2 b = (ca + 1 >= 0 && ca + 1 < NCOLS) ? xrow[ca + 1] : make_float2(0.f, 0.f);
            v[q] = make_float4(a.x, a.y, b.x, b.y);
        }
    }

    // out_i (i=0,1), tap k: column c0+i+k-5 -> window j = i + k + 1 (j = 1..12)
    // P[i] = sum_k xr_j * (wr_k, wi_k);  Q[i] = sum_k xi_j * (wr_k, wi_k)
    u64 P0 = 0ull, P1 = 0ull, Q0 = 0ull, Q1 = 0ull;
#pragma unroll
    for (int j = 1; j <= 12; j++) {
        const float4 w4 = v[j >> 1];
        const float re = (j & 1) ? w4.z : w4.x;
        const float im = (j & 1) ? w4.w : w4.y;
        const u64 xrr = pack2(re, re);
        const u64 xii = pack2(im, im);
        {   // i = 0: k = j - 1, valid for j = 1..11
            const int k = j - 1;
            if (k >= 0 && k < NFILT) {
                P0 = fma2(xrr, A[k], P0);
                Q0 = fma2(xii, A[k], Q0);
            }
        }
        {   // i = 1: k = j - 2, valid for j = 2..12
            const int k = j - 2;
            if (k >= 0 && k < NFILT) {
                P1 = fma2(xrr, A[k], P1);
                Q1 = fma2(xii, A[k], Q1);
            }
        }
    }

    // out = (P.lo - Q.hi, P.hi + Q.lo)
    float p0r, p0i, q0r, q0i, p1r, p1i, q1r, q1i;
    unpack2(P0, p0r, p0i); unpack2(Q0, q0r, q0i);
    unpack2(P1, p1r, p1i); unpack2(Q1, q1r, q1i);
    float4 o = make_float4(p0r - q0i, p0i + q0r, p1r - q1i, p1i + q1r);
    *(float4*)(yrow + c0) = o;
}

extern "C" void kernel_launch(void* const* d_in, const int* in_sizes, int n_in,
                              void* d_out, int out_size)
{
    const float2* X   = (const float2*)d_in[0];
    const float*  phi = (const float*)d_in[1];
    float2*       Y   = (float2*)d_out;

    dim3 grid(NCOLS / (TBLOCK * ITEMS), NROWS);   // 512 x 128
    fir_complex_dense_kernel<<<grid, TBLOCK>>>(X, phi, Y);
}

// round 5
// speedup vs baseline: 1.4267x; 1.4267x over previous
#include <cuda_runtime.h>

#define TBLOCK  256
#define NFILT   11
#define NCOLS   262144
#define NROWS   128
#define TILE    1024
#define TPB     8                 // tiles per block (pipelined)
#define SW      1040              // staged complexes per tile: [tile0-8, tile0+1032)
#define NF4ROW  (NCOLS / 2)       // float4s per row

typedef unsigned long long u64;

__device__ __forceinline__ u64 pack2(float lo, float hi) {
    u64 r; asm("mov.b64 %0, {%1, %2};" : "=l"(r) : "f"(lo), "f"(hi)); return r;
}
__device__ __forceinline__ void unpack2(u64 v, float& lo, float& hi) {
    asm("mov.b64 {%0, %1}, %2;" : "=f"(lo), "=f"(hi) : "l"(v));
}
__device__ __forceinline__ u64 fma2(u64 a, u64 b, u64 c) {
    u64 d; asm("fma.rn.f32x2 %0, %1, %2, %3;" : "=l"(d) : "l"(a), "l"(b), "l"(c)); return d;
}
__device__ __forceinline__ float4 ldz(const float4* x4, int u) {
    // SAME padding: zero outside the row
    if (u >= 0 && u < NF4ROW) return __ldg(x4 + u);
    return make_float4(0.f, 0.f, 0.f, 0.f);
}

__global__ void __launch_bounds__(TBLOCK) fir_pipe_kernel(
    const float2* __restrict__ X, const float* __restrict__ phi,
    float2* __restrict__ Y)
{
    __shared__ float s_re[2][SW];
    __shared__ float s_im[2][SW];

    const int tid = threadIdx.x;
    const int row = blockIdx.y;
    const float4* x4 = (const float4*)(X + (size_t)row * NCOLS);
    float2* yrow     = Y + (size_t)row * NCOLS;

    // Coefficients A[k] = (wr_k, wi_k) — phi's native layout.
    u64 A[NFILT];
#pragma unroll
    for (int k = 0; k < NFILT; k++) {
        float2 w = __ldg(((const float2*)phi) + k);
        A[k] = pack2(w.x, w.y);
    }

    const int tbase = blockIdx.x * TPB;   // first tile index (0..255) for this block

    // ---- Prologue: load + stage tile tbase into buffer 0 ----
    {
        const int f0 = tbase * 512 - 4;   // first float4 index: (tile0 - 8)/2
        float4 p0 = ldz(x4, f0 + tid);
        float4 p1 = ldz(x4, f0 + 256 + tid);
        float4 p2 = make_float4(0.f, 0.f, 0.f, 0.f);
        if (tid < 8) p2 = ldz(x4, f0 + 512 + tid);

        *(float2*)(&s_re[0][2 * tid])         = make_float2(p0.x, p0.z);
        *(float2*)(&s_im[0][2 * tid])         = make_float2(p0.y, p0.w);
        *(float2*)(&s_re[0][2 * (tid + 256)]) = make_float2(p1.x, p1.z);
        *(float2*)(&s_im[0][2 * (tid + 256)]) = make_float2(p1.y, p1.w);
        if (tid < 8) {
            *(float2*)(&s_re[0][2 * (tid + 512)]) = make_float2(p2.x, p2.z);
            *(float2*)(&s_im[0][2 * (tid + 512)]) = make_float2(p2.y, p2.w);
        }
    }
    __syncthreads();

    // ---- Pipelined main loop: prefetch i+1 (LDG), compute i, STS i+1, sync ----
    for (int it = 0; it < TPB; ++it) {
        const int  b    = it & 1;
        const bool more = (it + 1 < TPB);

        float4 q0 = make_float4(0.f, 0.f, 0.f, 0.f);
        float4 q1 = q0, q2 = q0;
        if (more) {
            const int f0 = (tbase + it + 1) * 512 - 4;
            q0 = ldz(x4, f0 + tid);
            q1 = ldz(x4, f0 + 256 + tid);
            if (tid < 8) q2 = ldz(x4, f0 + 512 + tid);
        }

        // ---- Compute tile (tbase+it) from buffer b (R2-proven core) ----
        {
            float re[17], im[17];
            const float4* pr = (const float4*)(&s_re[b][4 * tid]);
            const float4* pi = (const float4*)(&s_im[b][4 * tid]);
#pragma unroll
            for (int q = 0; q < 4; q++) {
                float4 vr = pr[q], vi = pi[q];
                re[4*q] = vr.x; re[4*q+1] = vr.y; re[4*q+2] = vr.z; re[4*q+3] = vr.w;
                im[4*q] = vi.x; im[4*q+1] = vi.y; im[4*q+2] = vi.z; im[4*q+3] = vi.w;
            }
            re[16] = s_re[b][4 * tid + 16];
            im[16] = s_im[b][4 * tid + 16];

            u64 P[4], Q[4];
#pragma unroll
            for (int i = 0; i < 4; i++) { P[i] = 0ull; Q[i] = 0ull; }

#pragma unroll
            for (int j = 3; j <= 16; j++) {
                u64 xrr = pack2(re[j], re[j]);
                u64 xii = pack2(im[j], im[j]);
#pragma unroll
                for (int i = 0; i < 4; i++) {
                    const int k = j - 3 - i;        // compile-time after unroll
                    if (k >= 0 && k < NFILT) {
                        P[i] = fma2(xrr, A[k], P[i]);
                        Q[i] = fma2(xii, A[k], Q[i]);
                    }
                }
            }

            const int c0 = (tbase + it) * TILE + 4 * tid;
            float4 o0, o1;
            float prr, pri, qir, qii;
            unpack2(P[0], prr, pri); unpack2(Q[0], qir, qii); o0.x = prr - qii; o0.y = pri + qir;
            unpack2(P[1], prr, pri); unpack2(Q[1], qir, qii); o0.z = prr - qii; o0.w = pri + qir;
            unpack2(P[2], prr, pri); unpack2(Q[2], qir, qii); o1.x = prr - qii; o1.y = pri + qir;
            unpack2(P[3], prr, pri); unpack2(Q[3], qir, qii); o1.z = prr - qii; o1.w = pri + qir;

            float4* yo = (float4*)(yrow + c0);
            yo[0] = o0;
            yo[1] = o1;
        }

        // ---- Stage tile (tbase+it+1) into the other buffer ----
        if (more) {
            const int nb = b ^ 1;
            *(float2*)(&s_re[nb][2 * tid])         = make_float2(q0.x, q0.z);
            *(float2*)(&s_im[nb][2 * tid])         = make_float2(q0.y, q0.w);
            *(float2*)(&s_re[nb][2 * (tid + 256)]) = make_float2(q1.x, q1.z);
            *(float2*)(&s_im[nb][2 * (tid + 256)]) = make_float2(q1.y, q1.w);
            if (tid < 8) {
                *(float2*)(&s_re[nb][2 * (tid + 512)]) = make_float2(q2.x, q2.z);
                *(float2*)(&s_im[nb][2 * (tid + 512)]) = make_float2(q2.y, q2.w);
            }
        }
        __syncthreads();
    }
}

extern "C" void kernel_launch(void* const* d_in, const int* in_sizes, int n_in,
                              void* d_out, int out_size)
{
    const float2* X   = (const float2*)d_in[0];
    const float*  phi = (const float*)d_in[1];
    float2*       Y   = (float2*)d_out;

    dim3 grid(NCOLS / (TILE * TPB), NROWS);   // (32, 128)
    fir_pipe_kernel<<<grid, TBLOCK>>>(X, phi, Y);
}

// round 6
// speedup vs baseline: 1.5916x; 1.1155x over previous
#include <cuda_runtime.h>

#define TBLOCK  256
#define NFILT   11
#define NCOLS   262144
#define NROWS   128
#define TILE    1024
#define TPB     8                  // tiles per block (pipelined)
#define SW      1040               // staged complexes per tile: cols [tile0-6, tile0+1034)
#define NF4ROW  (NCOLS / 2)        // float4s per row

typedef unsigned long long u64;

__device__ __forceinline__ u64 pack2(float lo, float hi) {
    u64 r; asm("mov.b64 %0, {%1, %2};" : "=l"(r) : "f"(lo), "f"(hi)); return r;
}
__device__ __forceinline__ void unpack2(u64 v, float& lo, float& hi) {
    asm("mov.b64 {%0, %1}, %2;" : "=f"(lo), "=f"(hi) : "l"(v));
}
__device__ __forceinline__ u64 fma2(u64 a, u64 b, u64 c) {
    u64 d; asm("fma.rn.f32x2 %0, %1, %2, %3;" : "=l"(d) : "l"(a), "l"(b), "l"(c)); return d;
}
__device__ __forceinline__ float4 ldz(const float4* x4, int u) {
    // SAME padding: zeros outside the row
    if (u >= 0 && u < NF4ROW) return __ldg(x4 + u);
    return make_float4(0.f, 0.f, 0.f, 0.f);
}

__global__ void __launch_bounds__(TBLOCK) fir_pipe2_kernel(
    const float2* __restrict__ X, const float* __restrict__ phi,
    float2* __restrict__ Y)
{
    __shared__ float s_re[2][SW];
    __shared__ float s_im[2][SW];

    const int tid = threadIdx.x;
    const int row = blockIdx.y;
    const float4* x4 = (const float4*)(X + (size_t)row * NCOLS);
    float2* yrow     = Y + (size_t)row * NCOLS;

    // Coefficients A[k] = (wr_k, wi_k) — phi's native layout.
    u64 A[NFILT];
#pragma unroll
    for (int k = 0; k < NFILT; k++) {
        float2 w = __ldg(((const float2*)phi) + k);
        A[k] = pack2(w.x, w.y);
    }

    const int tbase = blockIdx.x * TPB;

    // Staging registers hold ONE tile (the next to be stored).
    float4 r0, r1, r2;

    // smem index j <-> column tile0 - 6 + j. float4 f of tile t starts at
    // global float4 index f0(t) = t*512 - 3 (complexes 2*f0, 2*f0+1).
    #define LOAD_TILE(t)  do {                                   \
        const int f0 = (tbase + (t)) * 512 - 3;                  \
        r0 = ldz(x4, f0 + tid);                                  \
        r1 = ldz(x4, f0 + 256 + tid);                            \
        r2 = (tid < 8) ? ldz(x4, f0 + 512 + tid)                 \
                       : make_float4(0.f, 0.f, 0.f, 0.f);        \
    } while (0)

    #define STORE_TILE(buf) do {                                                  \
        *(float2*)(&s_re[buf][2 * tid])         = make_float2(r0.x, r0.z);        \
        *(float2*)(&s_im[buf][2 * tid])         = make_float2(r0.y, r0.w);        \
        *(float2*)(&s_re[buf][2 * (tid + 256)]) = make_float2(r1.x, r1.z);        \
        *(float2*)(&s_im[buf][2 * (tid + 256)]) = make_float2(r1.y, r1.w);        \
        if (tid < 8) {                                                            \
            *(float2*)(&s_re[buf][2 * (tid + 512)]) = make_float2(r2.x, r2.z);    \
            *(float2*)(&s_im[buf][2 * (tid + 512)]) = make_float2(r2.y, r2.w);    \
        }                                                                          \
    } while (0)

    // ---- Prologue: tile 0 staged, tile 1 loaded into registers ----
    LOAD_TILE(0);
    STORE_TILE(0);
    LOAD_TILE(1);
    __syncthreads();

    for (int it = 0; it < TPB; ++it) {
        const int b = it & 1;

        // Stage tile it+1 (regs -> other smem buffer), then start LDG of it+2.
        if (it + 1 < TPB) {
            STORE_TILE(b ^ 1);
            if (it + 2 < TPB) LOAD_TILE(it + 2);
        }

        // ---- Compute tile it from buffer b ----
        // Window floats [4t, 4t+15]; taps use j = i + k + 1 in [4t+1, 4t+14].
        float re[16], im[16];
        {
            const float4* pr = (const float4*)(&s_re[b][4 * tid]);
            const float4* pi = (const float4*)(&s_im[b][4 * tid]);
#pragma unroll
            for (int q = 0; q < 4; q++) {
                float4 vr = pr[q], vi = pi[q];
                re[4*q] = vr.x; re[4*q+1] = vr.y; re[4*q+2] = vr.z; re[4*q+3] = vr.w;
                im[4*q] = vi.x; im[4*q+1] = vi.y; im[4*q+2] = vi.z; im[4*q+3] = vi.w;
            }
        }

        u64 P[4], Q[4];
#pragma unroll
        for (int i = 0; i < 4; i++) { P[i] = 0ull; Q[i] = 0ull; }

#pragma unroll
        for (int j = 1; j <= 14; j++) {
            u64 xrr = pack2(re[j], re[j]);
            u64 xii = pack2(im[j], im[j]);
#pragma unroll
            for (int i = 0; i < 4; i++) {
                const int k = j - 1 - i;            // compile-time after unroll
                if (k >= 0 && k < NFILT) {
                    P[i] = fma2(xrr, A[k], P[i]);
                    Q[i] = fma2(xii, A[k], Q[i]);
                }
            }
        }

        // out = (P.lo - Q.hi, P.hi + Q.lo)
        const int c0 = (tbase + it) * TILE + 4 * tid;
        float4 o0, o1;
        float prr, pri, qir, qii;
        unpack2(P[0], prr, pri); unpack2(Q[0], qir, qii); o0.x = prr - qii; o0.y = pri + qir;
        unpack2(P[1], prr, pri); unpack2(Q[1], qir, qii); o0.z = prr - qii; o0.w = pri + qir;
        unpack2(P[2], prr, pri); unpack2(Q[2], qir, qii); o1.x = prr - qii; o1.y = pri + qir;
        unpack2(P[3], prr, pri); unpack2(Q[3], qir, qii); o1.z = prr - qii; o1.w = pri + qir;

        float4* yo = (float4*)(yrow + c0);
        yo[0] = o0;
        yo[1] = o1;

        __syncthreads();
    }
    #undef LOAD_TILE
    #undef STORE_TILE
}

extern "C" void kernel_launch(void* const* d_in, const int* in_sizes, int n_in,
                              void* d_out, int out_size)
{
    const float2* X   = (const float2*)d_in[0];
    const float*  phi = (const float*)d_in[1];
    float2*       Y   = (float2*)d_out;

    dim3 grid(NCOLS / (TILE * TPB), NROWS);   // (32, 128)
    fir_pipe2_kernel<<<grid, TBLOCK>>>(X, phi, Y);
}